// round 1
// baseline (speedup 1.0000x reference)
#include <cuda_runtime.h>
#include <math.h>

// Problem constants
#define HH 128
#define WW 128
#define BATCH 2
#define CFEAT 128
#define PLANE (HH * WW)

// ---------------------------------------------------------------------------
// Scratch (device globals; no allocation allowed)
// ---------------------------------------------------------------------------
__device__ float g_tmp1[BATCH * 64 * PLANE];      // conv1 out  (B,64,H,W)
__device__ float g_off [BATCH * 18 * PLANE];      // offsets    (B,18,H,W)
__device__ float g_tmp2[BATCH * CFEAT * PLANE];   // deform out (B,128,H,W)
__device__ float g_tmp3[BATCH * 64 * PLANE];      // fh conv1   (B,64,H,W)
__device__ float g_dwt [9 * CFEAT * CFEAT];       // dweight transposed [k][c][o]

// ---------------------------------------------------------------------------
// Transpose deform weights: dweight (O=128, C=128, 3,3) -> dwt[k][c][o]
// ---------------------------------------------------------------------------
__global__ void wt_transpose_kernel(const float* __restrict__ dw) {
    int t = blockIdx.x * blockDim.x + threadIdx.x;
    if (t >= CFEAT * CFEAT * 9) return;
    int o  = t / (CFEAT * 9);
    int r  = t % (CFEAT * 9);
    int c  = r / 9;
    int kk = r % 9;
    g_dwt[(kk * CFEAT + c) * CFEAT + o] = dw[t];
}

// ---------------------------------------------------------------------------
// 3x3 SAME conv, Cout = 64, optionally concatenated second input, optional relu
// Block: 32(w) x 4(h) pixels, all 64 out channels. 256 threads:
//   wx = tid&31 (pixel w), og = tid>>5 (8 groups of 8 out channels)
// Register tile per thread: 4(h) x 8(o) accumulators.
// ---------------------------------------------------------------------------
template <int CINA, int CINB, bool RELU>
__global__ __launch_bounds__(256)
void conv3x3_c64_kernel(const float* __restrict__ inA, const float* __restrict__ inB,
                        const float* __restrict__ wgt, const float* __restrict__ bias,
                        float* __restrict__ out) {
    constexpr int CIN = CINA + CINB;
    constexpr int CB = 4;
    __shared__ float s_in[CB][6][34];
    __shared__ float s_w[CB][64][9];

    const int tid = threadIdx.x;
    const int wx = tid & 31;
    const int og = tid >> 5;
    const int w0 = blockIdx.x * 32;
    const int h0 = blockIdx.y * 4;
    const int b  = blockIdx.z;

    float acc[4][8];
#pragma unroll
    for (int i = 0; i < 4; i++)
#pragma unroll
        for (int j = 0; j < 8; j++) acc[i][j] = 0.f;

    for (int c0 = 0; c0 < CIN; c0 += CB) {
        // ---- stage input patch (CB channels, 6 rows x 34 cols, zero-padded)
        for (int i = tid; i < CB * 6 * 34; i += 256) {
            int cc  = i / 204;
            int rem = i % 204;
            int r   = rem / 34;
            int col = rem % 34;
            int c = c0 + cc;
            int y = h0 - 1 + r;
            int x = w0 - 1 + col;
            float v = 0.f;
            if (c < CIN && y >= 0 && y < HH && x >= 0 && x < WW) {
                v = (c < CINA) ? inA[((b * CINA + c) * HH + y) * WW + x]
                               : inB[((b * CINB + (c - CINA)) * HH + y) * WW + x];
            }
            s_in[cc][r][col] = v;
        }
        // ---- stage weights (CB x 64 x 9)
        for (int i = tid; i < CB * 64 * 9; i += 256) {
            int cc  = i / 576;
            int rem = i % 576;
            int o   = rem / 9;
            int kk  = rem % 9;
            int c = c0 + cc;
            s_w[cc][o][kk] = (c < CIN) ? wgt[(o * CIN + c) * 9 + kk] : 0.f;
        }
        __syncthreads();

#pragma unroll
        for (int cc = 0; cc < CB; cc++) {
#pragma unroll
            for (int kh = 0; kh < 3; kh++) {
#pragma unroll
                for (int kw = 0; kw < 3; kw++) {
                    float wv[8];
#pragma unroll
                    for (int j = 0; j < 8; j++) wv[j] = s_w[cc][og * 8 + j][kh * 3 + kw];
                    float iv[4];
#pragma unroll
                    for (int i = 0; i < 4; i++) iv[i] = s_in[cc][i + kh][wx + kw];
#pragma unroll
                    for (int i = 0; i < 4; i++)
#pragma unroll
                        for (int j = 0; j < 8; j++) acc[i][j] += iv[i] * wv[j];
                }
            }
        }
        __syncthreads();
    }

#pragma unroll
    for (int j = 0; j < 8; j++) {
        int o = og * 8 + j;
        float bv = bias[o];
#pragma unroll
        for (int i = 0; i < 4; i++) {
            float v = acc[i][j] + bv;
            if (RELU) v = fmaxf(v, 0.f);
            out[((b * 64 + o) * HH + (h0 + i)) * WW + w0 + wx] = v;
        }
    }
}

// ---------------------------------------------------------------------------
// 3x3 SAME conv, CIN=64, small Cout (<=18), optional residual add.
// Block: 32(w) x 8(h) pixels; each thread computes all COUT channels of 1 px.
// ---------------------------------------------------------------------------
template <int COUT, bool RES>
__global__ __launch_bounds__(256)
void conv3x3_small_kernel(const float* __restrict__ in, const float* __restrict__ wgt,
                          const float* __restrict__ bias, const float* __restrict__ res,
                          float* __restrict__ out) {
    constexpr int CIN = 64;
    constexpr int CB = 4;
    __shared__ float s_in[CB][10][34];
    __shared__ float s_w[CB][COUT * 9];

    const int tid = threadIdx.x;
    const int wx = tid & 31;
    const int hy = tid >> 5;
    const int w0 = blockIdx.x * 32;
    const int h0 = blockIdx.y * 8;
    const int b  = blockIdx.z;

    float acc[COUT];
#pragma unroll
    for (int o = 0; o < COUT; o++) acc[o] = 0.f;

    for (int c0 = 0; c0 < CIN; c0 += CB) {
        for (int i = tid; i < CB * 10 * 34; i += 256) {
            int cc  = i / 340;
            int rem = i % 340;
            int r   = rem / 34;
            int col = rem % 34;
            int y = h0 - 1 + r;
            int x = w0 - 1 + col;
            float v = 0.f;
            if (y >= 0 && y < HH && x >= 0 && x < WW)
                v = in[((b * CIN + c0 + cc) * HH + y) * WW + x];
            s_in[cc][r][col] = v;
        }
        for (int i = tid; i < CB * COUT * 9; i += 256) {
            int cc  = i / (COUT * 9);
            int rem = i % (COUT * 9);
            int o   = rem / 9;
            int kk  = rem % 9;
            s_w[cc][rem] = wgt[(o * CIN + (c0 + cc)) * 9 + kk];
        }
        __syncthreads();

#pragma unroll
        for (int cc = 0; cc < CB; cc++) {
#pragma unroll
            for (int kh = 0; kh < 3; kh++) {
#pragma unroll
                for (int kw = 0; kw < 3; kw++) {
                    float iv = s_in[cc][hy + kh][wx + kw];
#pragma unroll
                    for (int o = 0; o < COUT; o++)
                        acc[o] += iv * s_w[cc][o * 9 + kh * 3 + kw];
                }
            }
        }
        __syncthreads();
    }

#pragma unroll
    for (int o = 0; o < COUT; o++) {
        float v = acc[o] + bias[o];
        int oi = ((b * COUT + o) * HH + (h0 + hy)) * WW + w0 + wx;
        if (RES) v += res[oi];
        out[oi] = v;
    }
}

// ---------------------------------------------------------------------------
// Deformable 3x3 conv: feat (B,128,H,W), offsets (B,18,H,W), dwt[k][c][o].
// Block = 32 pixels (one w-strip of one row) x all 128 out channels.
// Per k: stage w[k] (128x128) + bilinear-gathered samples (128x32) in smem,
// then a 128x128x32 FFMA GEMM with 4px x 4o register tiles (float4 LDS).
// Dynamic smem = 91,136 B.
// ---------------------------------------------------------------------------
__global__ __launch_bounds__(256)
void deform_kernel(const float* __restrict__ feat, const float* __restrict__ offs,
                   const float* __restrict__ dbias, float* __restrict__ out) {
    extern __shared__ float smem[];
    float* s_wk   = smem;                       // 16384 floats  [c][o]
    float* s_samp = smem + 16384;               //  4096 floats  [c][px]
    float* s_wt   = smem + 16384 + 4096;        //  1152 floats  [k][px][4]
    int*   s_idx  = (int*)(smem + 16384 + 4096 + 1152);  // 1152 ints

    const int tid = threadIdx.x;
    const int w0 = blockIdx.x * 32;
    const int h  = blockIdx.y;
    const int b  = blockIdx.z;

    // ---- precompute bilinear corners per (k, px)
    for (int task = tid; task < 288; task += 256) {
        int k  = task >> 5;
        int px = task & 31;
        int w = w0 + px;
        float offy = offs[((b * 18 + 2 * k)     * HH + h) * WW + w];
        float offx = offs[((b * 18 + 2 * k + 1) * HH + h) * WW + w];
        float fy = (float)(h + k / 3 - 1) + offy;
        float fx = (float)(w + k % 3 - 1) + offx;
        float y0f = floorf(fy), x0f = floorf(fx);
        float ly = fy - y0f, lx = fx - x0f;
        int y0 = (int)y0f, x0 = (int)x0f;
        float wts[4] = {(1.f - ly) * (1.f - lx), (1.f - ly) * lx,
                        ly * (1.f - lx),          ly * lx};
        int ys[4] = {y0, y0, y0 + 1, y0 + 1};
        int xs[4] = {x0, x0 + 1, x0, x0 + 1};
#pragma unroll
        for (int c4 = 0; c4 < 4; c4++) {
            bool valid = (ys[c4] >= 0) && (ys[c4] < HH) && (xs[c4] >= 0) && (xs[c4] < WW);
            s_idx[(k * 32 + px) * 4 + c4] = valid ? (ys[c4] * WW + xs[c4]) : 0;
            s_wt [(k * 32 + px) * 4 + c4] = valid ? wts[c4] : 0.f;
        }
    }

    float acc[4][4];
#pragma unroll
    for (int i = 0; i < 4; i++)
#pragma unroll
        for (int j = 0; j < 4; j++) acc[i][j] = 0.f;

    const int pxg = tid & 7;    // 8 groups of 4 pixels (GEMM)
    const int ogm = tid >> 3;   // 32 groups of 4 out channels (GEMM)
    const int gpx = tid & 31;   // gather: pixel
    const int gog = tid >> 5;   // gather: channel group
    const float* fbase = feat + (size_t)b * CFEAT * PLANE;

    __syncthreads();

    for (int k = 0; k < 9; k++) {
        // stage weights for this k (contiguous [c][o])
        const float* wk = g_dwt + k * CFEAT * CFEAT;
        for (int i = tid; i < CFEAT * CFEAT; i += 256) s_wk[i] = wk[i];

        // bilinear gather: thread handles px=gpx, channels gog + 8*j
        int   i0 = s_idx[(k * 32 + gpx) * 4 + 0];
        int   i1 = s_idx[(k * 32 + gpx) * 4 + 1];
        int   i2 = s_idx[(k * 32 + gpx) * 4 + 2];
        int   i3 = s_idx[(k * 32 + gpx) * 4 + 3];
        float q0 = s_wt [(k * 32 + gpx) * 4 + 0];
        float q1 = s_wt [(k * 32 + gpx) * 4 + 1];
        float q2 = s_wt [(k * 32 + gpx) * 4 + 2];
        float q3 = s_wt [(k * 32 + gpx) * 4 + 3];
#pragma unroll
        for (int j = 0; j < 16; j++) {
            int c = gog + 8 * j;
            const float* fc = fbase + (size_t)c * PLANE;
            s_samp[c * 32 + gpx] = q0 * fc[i0] + q1 * fc[i1] + q2 * fc[i2] + q3 * fc[i3];
        }
        __syncthreads();

        // 128x128x32 GEMM slice
        const float4* sv4 = (const float4*)s_samp;
        const float4* wv4 = (const float4*)s_wk;
#pragma unroll 8
        for (int c = 0; c < CFEAT; c++) {
            float4 sv = sv4[c * 8 + pxg];
            float4 wv = wv4[c * 32 + ogm];
            float sx[4] = {sv.x, sv.y, sv.z, sv.w};
            float wv_[4] = {wv.x, wv.y, wv.z, wv.w};
#pragma unroll
            for (int i = 0; i < 4; i++)
#pragma unroll
                for (int j = 0; j < 4; j++) acc[i][j] += sx[i] * wv_[j];
        }
        __syncthreads();
    }

    // epilogue
#pragma unroll
    for (int j = 0; j < 4; j++) {
        int o = ogm * 4 + j;
        float bv = dbias[o];
#pragma unroll
        for (int i = 0; i < 4; i++) {
            out[(((size_t)b * CFEAT + o) * HH + h) * WW + w0 + pxg * 4 + i] = acc[i][j] + bv;
        }
    }
}

// ---------------------------------------------------------------------------
// Launch
// ---------------------------------------------------------------------------
extern "C" void kernel_launch(void* const* d_in, const int* in_sizes, int n_in,
                              void* d_out, int out_size) {
    const float* feat    = (const float*)d_in[0];
    const float* flow    = (const float*)d_in[1];
    const float* off_w1  = (const float*)d_in[2];
    const float* off_b1  = (const float*)d_in[3];
    const float* off_w2  = (const float*)d_in[4];
    const float* off_b2  = (const float*)d_in[5];
    const float* dweight = (const float*)d_in[6];
    const float* dbias   = (const float*)d_in[7];
    const float* fh_w1   = (const float*)d_in[8];
    const float* fh_b1   = (const float*)d_in[9];
    const float* fh_w2   = (const float*)d_in[10];
    const float* fh_b2   = (const float*)d_in[11];
    float* out = (float*)d_out;

    float *tmp1, *off, *tmp2, *tmp3;
    cudaGetSymbolAddress((void**)&tmp1, g_tmp1);
    cudaGetSymbolAddress((void**)&off,  g_off);
    cudaGetSymbolAddress((void**)&tmp2, g_tmp2);
    cudaGetSymbolAddress((void**)&tmp3, g_tmp3);

    const int DEFORM_SMEM = (16384 + 4096 + 1152 + 1152) * 4;  // 91136 B
    cudaFuncSetAttribute(deform_kernel, cudaFuncAttributeMaxDynamicSharedMemorySize,
                         DEFORM_SMEM);

    // 1. transpose deform weights -> [k][c][o]
    wt_transpose_kernel<<<(CFEAT * CFEAT * 9 + 255) / 256, 256>>>(dweight);

    // 2. conv1: concat(feat, flow) (130ch) -> 64ch, relu
    conv3x3_c64_kernel<128, 2, true><<<dim3(4, 32, BATCH), 256>>>(
        feat, flow, off_w1, off_b1, tmp1);

    // 3. conv2: 64 -> 18 (offsets)
    conv3x3_small_kernel<18, false><<<dim3(4, 16, BATCH), 256>>>(
        tmp1, off_w2, off_b2, nullptr, off);

    // 4. deformable conv: feat + offsets -> 128ch
    deform_kernel<<<dim3(4, 128, BATCH), 256, DEFORM_SMEM>>>(feat, off, dbias, tmp2);

    // 5. fh conv1: 128 -> 64, relu
    conv3x3_c64_kernel<128, 0, true><<<dim3(4, 32, BATCH), 256>>>(
        tmp2, tmp2, fh_w1, fh_b1, tmp3);

    // 6. fh conv2: 64 -> 2, + flow residual
    conv3x3_small_kernel<2, true><<<dim3(4, 16, BATCH), 256>>>(
        tmp3, fh_w2, fh_b2, flow, out);
}